// round 14
// baseline (speedup 1.0000x reference)
#include <cuda_runtime.h>
#include <cuda_bf16.h>
#include <math.h>
#include <stdint.h>

#define D_MODEL 1024
#define NHEAD 16
#define HD 64
#define BATCH 8
#define TQ 1024
#define TK 1024
#define WSZ (D_MODEL * D_MODEL)

// Scratch (static __device__ arrays; no allocation allowed)
__device__ float g_Q[BATCH * TQ * D_MODEL];
__device__ float g_K[BATCH * TK * D_MODEL];
__device__ float g_V[BATCH * TK * D_MODEL];
__device__ float g_O[BATCH * TQ * D_MODEL];
__device__ float g_L[BATCH * NHEAD * TQ];
__device__ __nv_bfloat16 g_E[BATCH * NHEAD * TQ * TK];   // unnormalized exp(scores)
__device__ float g_Ar[BATCH * TQ * D_MODEL];             // tf32-rounded query
__device__ float g_Mr[BATCH * TK * D_MODEL];             // tf32-rounded memory
__device__ float g_Wr[4 * WSZ];                          // tf32-rounded Wq,Wk,Wv,Wo

__device__ __forceinline__ uint32_t smem_u32(const void* p) {
    uint32_t a;
    asm("{ .reg .u64 t; cvta.to.shared.u64 t, %1; cvt.u32.u64 %0, t; }"
        : "=r"(a) : "l"(p));
    return a;
}

__device__ __forceinline__ uint32_t cvt_tf32(float f) {
    uint32_t o;
    asm("cvt.rna.tf32.f32 %0, %1;" : "=r"(o) : "f"(f));
    return o;
}
__device__ __forceinline__ float tf32f(float f) {
    return __uint_as_float(cvt_tf32(f));
}

#define MMA_TF32(acc, a0, a1, a2, a3, b0, b1)                                   \
    asm volatile(                                                               \
        "mma.sync.aligned.m16n8k8.row.col.f32.tf32.tf32.f32 "                   \
        "{%0,%1,%2,%3}, {%4,%5,%6,%7}, {%8,%9}, {%0,%1,%2,%3};"                 \
        : "+f"((acc)[0]), "+f"((acc)[1]), "+f"((acc)[2]), "+f"((acc)[3])        \
        : "r"(a0), "r"(a1), "r"(a2), "r"(a3), "r"(b0), "r"(b1))

#define CP_ASYNC16(dst, src)                                                    \
    asm volatile("cp.async.cg.shared.global [%0], [%1], 16;"                    \
                 :: "r"(dst), "l"(src))
#define CP_COMMIT() asm volatile("cp.async.commit_group;" ::: "memory")
#define CP_WAIT1()  asm volatile("cp.async.wait_group 1;" ::: "memory")

// ---------------------------------------------------------------------------
// Pre-round fp32 -> tf32(rna) bits (vectorized)
// ---------------------------------------------------------------------------
__global__ __launch_bounds__(256) void round_tf32_kernel(
    const float* __restrict__ src, float* __restrict__ dst)
{
    const int i = (blockIdx.x * 256 + threadIdx.x) * 4;
    float4 v = *(const float4*)(src + i);
    float4 p;
    p.x = tf32f(v.x); p.y = tf32f(v.y); p.z = tf32f(v.z); p.w = tf32f(v.w);
    *(float4*)(dst + i) = p;
}

// ---------------------------------------------------------------------------
// GEMM v3: cp.async 3-stage pipeline.  C[M,1024] = A @ W^T + bias.
// Inputs A, W must be PRE-ROUNDED to tf32. CTA tile 128x128, BK=16,
// 128 threads (4 warps), warp tile 64x64. Smem rows stride 20 floats
// (80B, 16B-aligned; fragment reads conflict-free).
// ---------------------------------------------------------------------------
#define G3ROW 20
#define G3STG (128 * G3ROW)                  // floats per operand per stage
#define GEMM3_DSMEM (6 * G3STG * 4)          // 3 stages x 2 operands = 61440 B

__device__ __forceinline__ void gemm3_issue(
    const float* __restrict__ Ag, const float* __restrict__ Wg,
    uint32_t sbase, int it, int t)
{
    const int s = it - (it / 3) * 3;
    const int k0 = it * 16;
    const uint32_t dA = sbase + (uint32_t)(s * G3STG * 4) + (uint32_t)(t * 80);
    const float* srcA = Ag + (size_t)t * D_MODEL + k0;
#pragma unroll
    for (int ch = 0; ch < 4; ++ch) CP_ASYNC16(dA + ch * 16, srcA + ch * 4);
    const uint32_t dW = sbase + (uint32_t)((3 * G3STG + s * G3STG) * 4) + (uint32_t)(t * 80);
    const float* srcW = Wg + (size_t)t * D_MODEL + k0;
#pragma unroll
    for (int ch = 0; ch < 4; ++ch) CP_ASYNC16(dW + ch * 16, srcW + ch * 4);
}

__device__ __forceinline__ void gemm3_core(
    const float* __restrict__ A, const float* __restrict__ W,
    const float* __restrict__ bias, float* __restrict__ C,
    float* smf, int bx, int by)
{
    const int t = threadIdx.x;
    const int lane = t & 31, w = t >> 5;
    const int wm = (w & 1) * 64;
    const int wn = (w >> 1) * 64;
    const int g = lane >> 2, tg = lane & 3;

    const float* Ag = A + (size_t)(by * 128) * D_MODEL;
    const float* Wg = W + (size_t)(bx * 128) * D_MODEL;
    const uint32_t sbase = smem_u32(smf);

    float acc[4][8][4];
#pragma unroll
    for (int mt = 0; mt < 4; ++mt)
#pragma unroll
        for (int nt = 0; nt < 8; ++nt)
#pragma unroll
            for (int r = 0; r < 4; ++r) acc[mt][nt][r] = 0.f;

    const int NIT = D_MODEL / 16;   // 64

    gemm3_issue(Ag, Wg, sbase, 0, t); CP_COMMIT();
    gemm3_issue(Ag, Wg, sbase, 1, t); CP_COMMIT();

    for (int it = 0; it < NIT; ++it) {
        CP_WAIT1();
        __syncthreads();
        {
            const int s = it - (it / 3) * 3;
            const float* as = smf + s * G3STG;
            const float* ws = smf + 3 * G3STG + s * G3STG;
#pragma unroll
            for (int kk = 0; kk < 2; ++kk) {
                const int k0 = kk * 8;
                uint32_t af[4][4];
#pragma unroll
                for (int mt = 0; mt < 4; ++mt) {
                    const int r0 = wm + mt * 16 + g;
                    af[mt][0] = __float_as_uint(as[r0 * G3ROW + k0 + tg]);
                    af[mt][1] = __float_as_uint(as[(r0 + 8) * G3ROW + k0 + tg]);
                    af[mt][2] = __float_as_uint(as[r0 * G3ROW + k0 + 4 + tg]);
                    af[mt][3] = __float_as_uint(as[(r0 + 8) * G3ROW + k0 + 4 + tg]);
                }
#pragma unroll
                for (int nt = 0; nt < 8; ++nt) {
                    const int c0 = wn + nt * 8 + g;
                    const uint32_t b0 = __float_as_uint(ws[c0 * G3ROW + k0 + tg]);
                    const uint32_t b1 = __float_as_uint(ws[c0 * G3ROW + k0 + 4 + tg]);
#pragma unroll
                    for (int mt = 0; mt < 4; ++mt)
                        MMA_TF32(acc[mt][nt], af[mt][0], af[mt][1], af[mt][2],
                                 af[mt][3], b0, b1);
                }
            }
        }
        __syncthreads();   // all warps done with stage (it+2)%3's old contents
        if (it + 2 < NIT) gemm3_issue(Ag, Wg, sbase, it + 2, t);
        CP_COMMIT();
    }

#pragma unroll
    for (int mt = 0; mt < 4; ++mt) {
        const int row0 = by * 128 + wm + mt * 16 + g;
#pragma unroll
        for (int nt = 0; nt < 8; ++nt) {
            const int col = bx * 128 + wn + nt * 8 + 2 * tg;
            const float2 b01 = *(const float2*)(bias + col);
            float2 v0, v1;
            v0.x = acc[mt][nt][0] + b01.x;
            v0.y = acc[mt][nt][1] + b01.y;
            v1.x = acc[mt][nt][2] + b01.x;
            v1.y = acc[mt][nt][3] + b01.y;
            *(float2*)(C + (size_t)row0 * D_MODEL + col) = v0;
            *(float2*)(C + (size_t)(row0 + 8) * D_MODEL + col) = v1;
        }
    }
}

// Fused Q/K/V projection: grid (8, 64, 3)
__global__ __launch_bounds__(128) void qkv_gemm_kernel(
    const float* __restrict__ bq, const float* __restrict__ bk,
    const float* __restrict__ bv)
{
    extern __shared__ float smf[];
    const int z = blockIdx.z;
    const float* A = (z == 0) ? g_Ar : g_Mr;
    const float* W = g_Wr + (size_t)z * WSZ;
    const float* bias = (z == 0) ? bq : ((z == 1) ? bk : bv);
    float* C = (z == 0) ? g_Q : ((z == 1) ? g_K : g_V);
    gemm3_core(A, W, bias, C, smf, blockIdx.x, blockIdx.y);
}

// Output projection: grid (8, 64)
__global__ __launch_bounds__(128) void out_gemm_kernel(
    const float* __restrict__ bo, float* __restrict__ out)
{
    extern __shared__ float smf[];
    gemm3_core(g_O, g_Wr + 3 * (size_t)WSZ, bo, out, smf, blockIdx.x, blockIdx.y);
}

// ---------------------------------------------------------------------------
// Flash-style attention on mma.sync tf32 (R6 structure — best measured).
// CTA = (qtile 128, head, batch), 256 threads = 8 warps; warp owns 16 q rows.
// Per k-tile (64 keys): S = Q K^T (mma), e = exp(S/8 + covbias),
// P staged via smem (tf32), E stored to g_E (bf16), O += P V (mma).
// O written tf32-rounded (feeds out_gemm's cp.async path).
// ---------------------------------------------------------------------------
#define ATTN2_SMEM_FLOATS (128 * 68 + 64 * 68 + 64 * 68 + 128 * 68 + 64 + 128)
#define ATTN2_DSMEM (ATTN2_SMEM_FLOATS * 4)

__global__ __launch_bounds__(256) void attn_mma_kernel(
    const float* __restrict__ coverage, const float* __restrict__ Wcov)
{
    extern __shared__ float sm[];
    float* Qs = sm;                   // [q=128][d stride 68] tf32 bits
    float* Ks = Qs + 128 * 68;        // [key=64][d stride 68] tf32 bits
    float* Vt = Ks + 64 * 68;         // [dv=64][key stride 68] tf32 bits
    float* Ps = Vt + 64 * 68;         // [q=128][key stride 68] tf32 bits
    float* cb = Ps + 128 * 68;        // [64]
    float* ls = cb + 64;              // [128]

    const int qt = blockIdx.x, h = blockIdx.y, b = blockIdx.z;
    const int tid = threadIdx.x;
    const int lane = tid & 31, w = tid >> 5;
    const int g = lane >> 2, tg = lane & 3;
    const int wq = w * 16;
    const float wch = __ldg(&Wcov[h]);

    // Q tile -> smem (tf32)
    {
        const float* Qg = g_Q + ((size_t)(b * TQ + qt * 128)) * D_MODEL + h * HD;
        for (int i = tid; i < 128 * 16; i += 256) {
            int q = i >> 4, d4 = (i & 15) << 2;
            float4 v = *(const float4*)(Qg + (size_t)q * D_MODEL + d4);
            float4 p;
            p.x = tf32f(v.x); p.y = tf32f(v.y); p.z = tf32f(v.z); p.w = tf32f(v.w);
            *(float4*)(Qs + q * 68 + d4) = p;
        }
    }
    if (tid < 128) ls[tid] = 0.f;

    float accO[8][4];
#pragma unroll
    for (int nt = 0; nt < 8; ++nt)
#pragma unroll
        for (int r = 0; r < 4; ++r) accO[nt][r] = 0.f;
    float lp0 = 0.f, lp1 = 0.f;

    __nv_bfloat16* Ebase = g_E + (((size_t)(b * NHEAD + h) * TQ + qt * 128)) * TK;

    for (int kt = 0; kt < 16; ++kt) {
        __syncthreads();
        const float* Kg = g_K + ((size_t)(b * TK + kt * 64)) * D_MODEL + h * HD;
        const float* Vg = g_V + ((size_t)(b * TK + kt * 64)) * D_MODEL + h * HD;
        for (int i = tid; i < 64 * 16; i += 256) {
            int k = i >> 4, d4 = (i & 15) << 2;
            float4 kv = *(const float4*)(Kg + (size_t)k * D_MODEL + d4);
            float4 pk;
            pk.x = tf32f(kv.x); pk.y = tf32f(kv.y);
            pk.z = tf32f(kv.z); pk.w = tf32f(kv.w);
            *(float4*)(Ks + k * 68 + d4) = pk;
            float4 vv = *(const float4*)(Vg + (size_t)k * D_MODEL + d4);
            Vt[(d4 + 0) * 68 + k] = tf32f(vv.x);
            Vt[(d4 + 1) * 68 + k] = tf32f(vv.y);
            Vt[(d4 + 2) * 68 + k] = tf32f(vv.z);
            Vt[(d4 + 3) * 68 + k] = tf32f(vv.w);
        }
        if (tid < 64) cb[tid] = __ldg(&coverage[b * TK + kt * 64 + tid]) * wch;
        __syncthreads();

        // S = Q K^T : warp rows wq..wq+15, 64 key cols
        float s[8][4];
#pragma unroll
        for (int nt = 0; nt < 8; ++nt)
#pragma unroll
            for (int r = 0; r < 4; ++r) s[nt][r] = 0.f;
#pragma unroll
        for (int kk = 0; kk < 8; ++kk) {
            const int k0 = kk * 8;
            const uint32_t a0 = __float_as_uint(Qs[(wq + g) * 68 + k0 + tg]);
            const uint32_t a1 = __float_as_uint(Qs[(wq + g + 8) * 68 + k0 + tg]);
            const uint32_t a2 = __float_as_uint(Qs[(wq + g) * 68 + k0 + 4 + tg]);
            const uint32_t a3 = __float_as_uint(Qs[(wq + g + 8) * 68 + k0 + 4 + tg]);
#pragma unroll
            for (int nt = 0; nt < 8; ++nt) {
                const uint32_t b0 = __float_as_uint(Ks[(nt * 8 + g) * 68 + k0 + tg]);
                const uint32_t b1 = __float_as_uint(Ks[(nt * 8 + g) * 68 + k0 + 4 + tg]);
                MMA_TF32(s[nt], a0, a1, a2, a3, b0, b1);
            }
        }

        // exp + coverage bias -> Ps (tf32) + E gmem (bf16 from registers)
        __nv_bfloat16* Eg = Ebase + kt * 64;
#pragma unroll
        for (int nt = 0; nt < 8; ++nt) {
            const int c = nt * 8 + 2 * tg;
            const float cb0 = cb[c], cb1 = cb[c + 1];
            const float e0 = __expf(fmaf(s[nt][0], 0.125f, cb0));
            const float e1 = __expf(fmaf(s[nt][1], 0.125f, cb1));
            const float e2 = __expf(fmaf(s[nt][2], 0.125f, cb0));
            const float e3 = __expf(fmaf(s[nt][3], 0.125f, cb1));
            lp0 += e0 + e1;
            lp1 += e2 + e3;
            float2 p0, p1;
            p0.x = tf32f(e0); p0.y = tf32f(e1);
            p1.x = tf32f(e2); p1.y = tf32f(e3);
            *(float2*)(Ps + (wq + g) * 68 + c) = p0;
            *(float2*)(Ps + (wq + g + 8) * 68 + c) = p1;
            __nv_bfloat162 q01 = __floats2bfloat162_rn(e0, e1);
            __nv_bfloat162 q23 = __floats2bfloat162_rn(e2, e3);
            *reinterpret_cast<uint32_t*>(Eg + (size_t)(wq + g) * TK + c) =
                *reinterpret_cast<uint32_t*>(&q01);
            *reinterpret_cast<uint32_t*>(Eg + (size_t)(wq + g + 8) * TK + c) =
                *reinterpret_cast<uint32_t*>(&q23);
        }
        __syncwarp();   // Ps rows are warp-private

        // O += P V : A = Ps (q x key), B = V^T fragments from Vt[dv][k]
#pragma unroll
        for (int kk = 0; kk < 8; ++kk) {
            const int k0 = kk * 8;
            const uint32_t a0 = __float_as_uint(Ps[(wq + g) * 68 + k0 + tg]);
            const uint32_t a1 = __float_as_uint(Ps[(wq + g + 8) * 68 + k0 + tg]);
            const uint32_t a2 = __float_as_uint(Ps[(wq + g) * 68 + k0 + 4 + tg]);
            const uint32_t a3 = __float_as_uint(Ps[(wq + g + 8) * 68 + k0 + 4 + tg]);
#pragma unroll
            for (int nt = 0; nt < 8; ++nt) {
                const uint32_t b0 =
                    __float_as_uint(Vt[(nt * 8 + g) * 68 + k0 + tg]);
                const uint32_t b1 =
                    __float_as_uint(Vt[(nt * 8 + g) * 68 + k0 + 4 + tg]);
                MMA_TF32(accO[nt], a0, a1, a2, a3, b0, b1);
            }
        }
    }

    // row-sum reduction across the quad lanes (tg), then smem atomics
    lp0 += __shfl_xor_sync(0xffffffffu, lp0, 1);
    lp0 += __shfl_xor_sync(0xffffffffu, lp0, 2);
    lp1 += __shfl_xor_sync(0xffffffffu, lp1, 1);
    lp1 += __shfl_xor_sync(0xffffffffu, lp1, 2);
    if (tg == 0) {
        atomicAdd(&ls[wq + g], lp0);
        atomicAdd(&ls[wq + g + 8], lp1);
    }
    __syncthreads();

    const float inv0 = 1.f / ls[wq + g];
    const float inv1 = 1.f / ls[wq + g + 8];
    float* Og = g_O + ((size_t)(b * TQ + qt * 128)) * D_MODEL + h * HD;
#pragma unroll
    for (int nt = 0; nt < 8; ++nt) {
        const int c = nt * 8 + 2 * tg;
        float2 o0, o1;
        o0.x = tf32f(accO[nt][0] * inv0); o0.y = tf32f(accO[nt][1] * inv0);
        o1.x = tf32f(accO[nt][2] * inv1); o1.y = tf32f(accO[nt][3] * inv1);
        *(float2*)(Og + (size_t)(wq + g) * D_MODEL + c) = o0;
        *(float2*)(Og + (size_t)(wq + g + 8) * D_MODEL + c) = o1;
    }
    if (tid < 128)
        g_L[((size_t)b * NHEAD + h) * TQ + qt * 128 + tid] = ls[tid];
}

// ---------------------------------------------------------------------------
// Coverage reduction: covout[b,k] += sum_{h,q} E[b,h,q,k] / (16 * l[b,h,q])
// ---------------------------------------------------------------------------
__global__ __launch_bounds__(256) void cov_reduce_kernel(float* __restrict__ covout)
{
    __shared__ float il[128];
    const int qc = blockIdx.x, h = blockIdx.y, b = blockIdx.z;
    const int tid = threadIdx.x;
    if (tid < 128)
        il[tid] = 1.f / (16.f * g_L[((size_t)b * NHEAD + h) * TQ + qc * 128 + tid]);
    __syncthreads();

    const __nv_bfloat16* E = g_E +
        ((size_t)(b * NHEAD + h) * TQ + qc * 128) * TK;
    const int k0 = tid * 4;
    float a0 = 0.f, a1 = 0.f, a2 = 0.f, a3 = 0.f;
#pragma unroll 4
    for (int q = 0; q < 128; ++q) {
        uint2 p = *reinterpret_cast<const uint2*>(E + (size_t)q * TK + k0);
        const float wq = il[q];
        __nv_bfloat162 lo = *reinterpret_cast<__nv_bfloat162*>(&p.x);
        __nv_bfloat162 hi = *reinterpret_cast<__nv_bfloat162*>(&p.y);
        a0 = fmaf(__bfloat162float(lo.x), wq, a0);
        a1 = fmaf(__bfloat162float(lo.y), wq, a1);
        a2 = fmaf(__bfloat162float(hi.x), wq, a2);
        a3 = fmaf(__bfloat162float(hi.y), wq, a3);
    }
    atomicAdd(&covout[b * TK + k0 + 0], a0);
    atomicAdd(&covout[b * TK + k0 + 1], a1);
    atomicAdd(&covout[b * TK + k0 + 2], a2);
    atomicAdd(&covout[b * TK + k0 + 3], a3);
}

__global__ void cov_init_kernel(const float* __restrict__ coverage,
                                float* __restrict__ covout)
{
    int i = blockIdx.x * blockDim.x + threadIdx.x;
    if (i < BATCH * TK) covout[i] = coverage[i];
}

// ---------------------------------------------------------------------------
extern "C" void kernel_launch(void* const* d_in, const int* in_sizes, int n_in,
                              void* d_out, int out_size)
{
    const float* query    = (const float*)d_in[0];
    const float* memory   = (const float*)d_in[1];
    const float* coverage = (const float*)d_in[2];
    const float* Wq = (const float*)d_in[3];
    const float* bq = (const float*)d_in[4];
    const float* Wk = (const float*)d_in[5];
    const float* bk = (const float*)d_in[6];
    const float* Wv = (const float*)d_in[7];
    const float* bv = (const float*)d_in[8];
    const float* Wo = (const float*)d_in[9];
    const float* bo = (const float*)d_in[10];
    const float* Wcov = (const float*)d_in[11];

    float* out = (float*)d_out;
    float* covout = out + (size_t)BATCH * TQ * D_MODEL;

    float *Arp, *Mrp, *Wrp;
    cudaGetSymbolAddress((void**)&Arp, g_Ar);
    cudaGetSymbolAddress((void**)&Mrp, g_Mr);
    cudaGetSymbolAddress((void**)&Wrp, g_Wr);

    cudaFuncSetAttribute(qkv_gemm_kernel, cudaFuncAttributeMaxDynamicSharedMemorySize,
                         GEMM3_DSMEM);
    cudaFuncSetAttribute(out_gemm_kernel, cudaFuncAttributeMaxDynamicSharedMemorySize,
                         GEMM3_DSMEM);
    cudaFuncSetAttribute(attn_mma_kernel, cudaFuncAttributeMaxDynamicSharedMemorySize,
                         ATTN2_DSMEM);

    const int NELT = BATCH * TQ * D_MODEL;   // 8M

    // pre-round inputs to tf32 (rna)
    round_tf32_kernel<<<NELT / 1024, 256>>>(query, Arp);
    round_tf32_kernel<<<NELT / 1024, 256>>>(memory, Mrp);
    round_tf32_kernel<<<WSZ / 1024, 256>>>(Wq, Wrp);
    round_tf32_kernel<<<WSZ / 1024, 256>>>(Wk, Wrp + WSZ);
    round_tf32_kernel<<<WSZ / 1024, 256>>>(Wv, Wrp + 2 * (size_t)WSZ);
    round_tf32_kernel<<<WSZ / 1024, 256>>>(Wo, Wrp + 3 * (size_t)WSZ);

    // fused Q/K/V projections
    qkv_gemm_kernel<<<dim3(D_MODEL / 128, (BATCH * TQ) / 128, 3), 128,
                      GEMM3_DSMEM>>>(bq, bk, bv);

    attn_mma_kernel<<<dim3(TQ / 128, NHEAD, BATCH), 256, ATTN2_DSMEM>>>(coverage, Wcov);

    out_gemm_kernel<<<dim3(D_MODEL / 128, (BATCH * TQ) / 128), 128,
                      GEMM3_DSMEM>>>(bo, out);

    cov_init_kernel<<<(BATCH * TK + 255) / 256, 256>>>(coverage, covout);
    cov_reduce_kernel<<<dim3(TQ / 128, NHEAD, BATCH), 256>>>(covout);
}